// round 2
// baseline (speedup 1.0000x reference)
#include <cuda_runtime.h>

// Problem constants (from reference): N=1024, DIM=201, G=200, R=72, C=4
#define NIMG 1024
#define DIMV 201
#define GG   200
#define RR   72
#define CC   4
#define RC   288   // R*C, contiguous innermost block of x per (n, g)

// Per-image loss scratch (device-global array: allocation-free, graph-safe).
__device__ float g_loss[NIMG];

// One block per image. 288 threads: tid = r*4 + c.
// Phase 1: softmax-expected grid position per (r,c) — coalesced over the
//          contiguous 288-float (r,c) plane for each channel g.
// Phase 2: threads 0..3 parse top/down per lane from labels.
// Phase 3: thread 0 computes the two-sided second-difference loss.
__global__ __launch_bounds__(RC) void pos_parse_kernel(
    const float* __restrict__ x, const int* __restrict__ labels)
{
    __shared__ float s_pos[RC];
    __shared__ int   s_top[CC];
    __shared__ int   s_down[CC];

    const int n   = blockIdx.x;
    const int tid = threadIdx.x;

    // ---- Phase 1: pos[tid] = sum_g g*exp(x) / sum_g exp(x) ----
    const float* xp = x + (size_t)n * DIMV * RC + tid;
    float s  = 0.0f;
    float sp = 0.0f;
    #pragma unroll 8
    for (int g = 0; g < GG; ++g) {
        float v = __expf(xp[(size_t)g * RC]);   // x ~ N(0,1): no overflow risk
        s  += v;
        sp  = fmaf(v, (float)g, sp);
    }
    s_pos[tid] = sp / s;

    // ---- Phase 2: parse top/down per column (lane) ----
    if (tid < CC) {
        const int* lp = labels + (size_t)n * RC + tid;  // labels are int32 (JAX x64 off)
        int  top = 0, first_trans = -1;
        bool any_valid = false, prev = false;
        bool v0 = false, v1 = false, vlast = false;
        #pragma unroll
        for (int r = 0; r < RR; ++r) {
            bool v = (lp[r * CC] < GG);   // valid = label < G
            if (v && !any_valid) { top = r; any_valid = true; }
            if (r > 0 && prev && !v && first_trans < 0) first_trans = r - 1;
            if (r == 0)      v0 = v;
            if (r == 1)      v1 = v;
            if (r == RR - 1) vlast = v;
            prev = v;
        }
        bool trans0 = v0 && !v1;                    // valid->invalid at row 0
        int down = trans0 ? 0
                 : (vlast ? (RR - 1)
                 : (first_trans >= 0 ? first_trans : 0));
        if (!any_valid) { top = 0; down = 0; }
        s_top[tid]  = top;
        s_down[tid] = down;
    }
    __syncthreads();

    // ---- Phase 3: per-image loss ----
    if (tid == 0) {
        int tl = max(s_top[0],  max(s_top[1],  s_top[2]));
        int dl = min(s_down[0], min(s_down[1], s_down[2]));
        int tr = max(s_top[1],  max(s_top[2],  s_top[3]));
        int dr = min(s_down[1], min(s_down[2], s_down[3]));
        bool al = (tl < dl);
        bool ar = (tr < dr);

        // loss_side * W_side = (s / W^2 / npairs) * W = s / W   (npairs == 1)
        float contrib = 0.0f;
        if (al) {
            float sl = 0.0f;
            for (int r = tl; r <= dl; ++r) {
                const float* p = &s_pos[r * CC];
                sl += fabsf(p[0] - 2.0f * p[1] + p[2]);   // dd column 0
            }
            contrib += sl / (float)(dl - tl + 1);
        }
        if (ar) {
            float sr = 0.0f;
            for (int r = tr; r <= dr; ++r) {
                const float* p = &s_pos[r * CC];
                sr += fabsf(p[1] - 2.0f * p[2] + p[3]);   // dd column 1
            }
            contrib += sr / (float)(dr - tr + 1);
        }
        float denom = (al && ar) ? (2.0f * (float)RR) : (float)RR;
        g_loss[n] = contrib / denom;
    }
}

// Deterministic fixed-order tree reduction: mean of nonzero per-image losses.
__global__ __launch_bounds__(NIMG) void reduce_kernel(float* __restrict__ out)
{
    __shared__ float ssum[NIMG];
    __shared__ int   scnt[NIMG];
    const int t = threadIdx.x;
    float v  = g_loss[t];
    ssum[t]  = v;
    scnt[t]  = (v != 0.0f) ? 1 : 0;
    __syncthreads();
    #pragma unroll
    for (int s = NIMG / 2; s > 0; s >>= 1) {
        if (t < s) {
            ssum[t] += ssum[t + s];
            scnt[t] += scnt[t + s];
        }
        __syncthreads();
    }
    if (t == 0) {
        out[0] = (scnt[0] > 0) ? (ssum[0] / (float)scnt[0]) : 0.0f;
    }
}

extern "C" void kernel_launch(void* const* d_in, const int* in_sizes, int n_in,
                              void* d_out, int out_size)
{
    const float* x      = (const float*)d_in[0];   // [1024, 201, 72, 4] f32
    const int*   labels = (const int*)d_in[1];     // [1024, 72, 4] int32
    float*       out    = (float*)d_out;           // scalar f32

    pos_parse_kernel<<<NIMG, RC>>>(x, labels);
    reduce_kernel<<<1, NIMG>>>(out);
}

// round 3
// speedup vs baseline: 1.1231x; 1.1231x over previous
#include <cuda_runtime.h>

// Problem constants: N=1024, DIM=201, G=200, R=72, C=4
#define NIMG 1024
#define DIMV 201
#define GG   200
#define RR   72
#define CC   4
#define RC   288    // R*C, contiguous innermost block of x per (n, g)
#define NGC  4      // g-chunks per image (200 / 50)
#define GPC  50     // channels per g-chunk
#define NSG  72     // slot-groups (288 slots / 4 per float4)

// Scratch (device globals: allocation-free, graph-safe).
__device__ float        g_loss[NIMG];
__device__ unsigned int g_count = 0;   // reset to 0 by the last block each run

// One block per image, 288 threads.
//  Phase 1: tid -> (gc = tid/72, sg = tid%72). Each thread float4-loads 50
//           channels for slots [4sg, 4sg+4), accumulating exp-sums. Partials
//           combined over gc in shared memory -> pos[288].
//  Phase 2: threads 0..3 parse top/down per lane from labels.
//  Phase 3: thread 0 computes the per-image loss.
//  Phase 4: last block reduces g_loss[0..1023] (deterministic fixed tree).
__global__ __launch_bounds__(RC) void lane_loss_kernel(
    const float* __restrict__ x, const int* __restrict__ labels,
    float* __restrict__ out)
{
    __shared__ float sS[NGC][RC];     // partial sum(exp)
    __shared__ float sP[NGC][RC];     // partial sum(g*exp)
    __shared__ float s_pos[RC];
    __shared__ int   s_top[CC];
    __shared__ int   s_down[CC];
    __shared__ bool  s_last;

    const int n   = blockIdx.x;
    const int tid = threadIdx.x;
    const int gc  = tid / NSG;        // 0..3
    const int sg  = tid % NSG;        // 0..71

    // ---- Phase 1: exp accumulation, float4 over 4 slots ----
    {
        const float4* xp = (const float4*)(x + (size_t)n * DIMV * RC) + sg;
        const int gbase = gc * GPC;
        float s0 = 0.f, s1 = 0.f, s2 = 0.f, s3 = 0.f;
        float p0 = 0.f, p1 = 0.f, p2 = 0.f, p3 = 0.f;
        #pragma unroll 5
        for (int i = 0; i < GPC; ++i) {
            const int g = gbase + i;
            float4 v = xp[(size_t)g * NSG];
            float gw = (float)g;
            float e0 = __expf(v.x), e1 = __expf(v.y);
            float e2 = __expf(v.z), e3 = __expf(v.w);
            s0 += e0; p0 = fmaf(e0, gw, p0);
            s1 += e1; p1 = fmaf(e1, gw, p1);
            s2 += e2; p2 = fmaf(e2, gw, p2);
            s3 += e3; p3 = fmaf(e3, gw, p3);
        }
        const int base = sg * 4;
        sS[gc][base + 0] = s0;  sP[gc][base + 0] = p0;
        sS[gc][base + 1] = s1;  sP[gc][base + 1] = p1;
        sS[gc][base + 2] = s2;  sP[gc][base + 2] = p2;
        sS[gc][base + 3] = s3;  sP[gc][base + 3] = p3;
    }

    // ---- Phase 2: parse top/down per lane (threads 0..3) ----
    if (tid < CC) {
        const int* lp = labels + (size_t)n * RC + tid;  // int32 labels
        int  top = 0, first_trans = -1;
        bool any_valid = false, prev = false;
        bool v0 = false, v1 = false, vlast = false;
        #pragma unroll
        for (int r = 0; r < RR; ++r) {
            bool v = (lp[r * CC] < GG);
            if (v && !any_valid) { top = r; any_valid = true; }
            if (r > 0 && prev && !v && first_trans < 0) first_trans = r - 1;
            if (r == 0)      v0 = v;
            if (r == 1)      v1 = v;
            if (r == RR - 1) vlast = v;
            prev = v;
        }
        bool trans0 = v0 && !v1;
        int down = trans0 ? 0
                 : (vlast ? (RR - 1)
                 : (first_trans >= 0 ? first_trans : 0));
        if (!any_valid) { top = 0; down = 0; }
        s_top[tid]  = top;
        s_down[tid] = down;
    }
    __syncthreads();

    // Combine gc-partials -> pos per slot
    {
        float s = sS[0][tid] + sS[1][tid] + sS[2][tid] + sS[3][tid];
        float p = sP[0][tid] + sP[1][tid] + sP[2][tid] + sP[3][tid];
        s_pos[tid] = p / s;
    }
    __syncthreads();

    // ---- Phase 3: per-image loss (thread 0) ----
    if (tid == 0) {
        int tl = max(s_top[0],  max(s_top[1],  s_top[2]));
        int dl = min(s_down[0], min(s_down[1], s_down[2]));
        int tr = max(s_top[1],  max(s_top[2],  s_top[3]));
        int dr = min(s_down[1], min(s_down[2], s_down[3]));
        bool al = (tl < dl);
        bool ar = (tr < dr);

        float contrib = 0.0f;
        if (al) {
            float sl = 0.0f;
            for (int r = tl; r <= dl; ++r) {
                const float* p = &s_pos[r * CC];
                sl += fabsf(p[0] - 2.0f * p[1] + p[2]);
            }
            contrib += sl / (float)(dl - tl + 1);
        }
        if (ar) {
            float sr = 0.0f;
            for (int r = tr; r <= dr; ++r) {
                const float* p = &s_pos[r * CC];
                sr += fabsf(p[1] - 2.0f * p[2] + p[3]);
            }
            contrib += sr / (float)(dr - tr + 1);
        }
        float denom = (al && ar) ? (2.0f * (float)RR) : (float)RR;
        g_loss[n] = contrib / denom;

        // Publish + count finished blocks (release via threadfence+atomic)
        __threadfence();
        unsigned int old = atomicAdd(&g_count, 1u);
        s_last = (old == NIMG - 1);
    }
    __syncthreads();

    // ---- Phase 4: last block reduces all per-image losses ----
    if (s_last) {
        float sum = 0.0f;
        int   cnt = 0;
        #pragma unroll
        for (int k = 0; k < 4; ++k) {
            int i = tid + k * RC;              // 288-stride, covers 0..1151
            if (i < NIMG) {
                float v = g_loss[i];
                sum += v;
                cnt += (v != 0.0f) ? 1 : 0;
            }
        }
        // warp reduce (fixed shuffle tree -> deterministic)
        #pragma unroll
        for (int o = 16; o > 0; o >>= 1) {
            sum += __shfl_down_sync(0xffffffffu, sum, o);
            cnt += __shfl_down_sync(0xffffffffu, cnt, o);
        }
        __shared__ float wsum[9];
        __shared__ int   wcnt[9];
        const int wid = tid >> 5, lid = tid & 31;
        if (lid == 0) { wsum[wid] = sum; wcnt[wid] = cnt; }
        __syncthreads();
        if (tid == 0) {
            float ts = 0.0f; int tc = 0;
            #pragma unroll
            for (int w = 0; w < 9; ++w) { ts += wsum[w]; tc += wcnt[w]; }
            out[0] = (tc > 0) ? (ts / (float)tc) : 0.0f;
            g_count = 0;   // reset for next graph replay (deterministic)
        }
    }
}

extern "C" void kernel_launch(void* const* d_in, const int* in_sizes, int n_in,
                              void* d_out, int out_size)
{
    const float* x      = (const float*)d_in[0];   // [1024, 201, 72, 4] f32
    const int*   labels = (const int*)d_in[1];     // [1024, 72, 4] int32
    float*       out    = (float*)d_out;           // scalar f32

    lane_loss_kernel<<<NIMG, RC>>>(x, labels, out);
}

// round 4
// speedup vs baseline: 1.1786x; 1.0494x over previous
#include <cuda_runtime.h>

// Problem constants: N=1024, DIM=201, G=200, R=72, C=4
#define NIMG 1024
#define DIMV 201
#define GG   200
#define RR   72
#define CC   4
#define RC   288    // R*C, contiguous innermost block of x per (n, g)
#define NGC  4      // g-chunks per image (200 / 50)
#define GPC  50     // channels per g-chunk
#define NSG  72     // slot-groups (288 slots / 4 per float4)
#define BATCH 10    // channels loaded per batch (front-batched LDG.128)
#define NBATCH (GPC / BATCH)

// Scratch (device globals: allocation-free, graph-safe).
__device__ float        g_loss[NIMG];
__device__ unsigned int g_count = 0;   // reset by last block each run

__global__ __launch_bounds__(RC) void lane_loss_kernel(
    const float* __restrict__ x, const int* __restrict__ labels,
    float* __restrict__ out)
{
    __shared__ float sS[NGC][RC];     // partial sum(exp)
    __shared__ float sP[NGC][RC];     // partial sum(g*exp)
    __shared__ float s_pos[RC];
    __shared__ int   s_top[CC];
    __shared__ int   s_down[CC];
    __shared__ bool  s_last;

    const int n   = blockIdx.x;
    const int tid = threadIdx.x;
    const int gc  = tid / NSG;        // 0..3
    const int sg  = tid % NSG;        // 0..71

    // ---- Phase 1: exp accumulation; 5 batches of 10 front-batched LDG.128 ----
    {
        // base pointer at (n, gc*GPC, sg*4); channel stride = NSG float4s (1152 B)
        const float4* xp = (const float4*)(x + (size_t)n * (DIMV * RC))
                           + (unsigned)(gc * GPC) * NSG + sg;
        float s0 = 0.f, s1 = 0.f, s2 = 0.f, s3 = 0.f;
        float p0 = 0.f, p1 = 0.f, p2 = 0.f, p3 = 0.f;
        float gw = (float)(gc * GPC);

        #pragma unroll
        for (int b = 0; b < NBATCH; ++b) {
            float4 v[BATCH];
            #pragma unroll
            for (int j = 0; j < BATCH; ++j)
                v[j] = xp[(unsigned)j * NSG];     // immediate offsets off one base
            xp += (unsigned)BATCH * NSG;

            #pragma unroll
            for (int j = 0; j < BATCH; ++j) {
                float e0 = __expf(v[j].x), e1 = __expf(v[j].y);
                float e2 = __expf(v[j].z), e3 = __expf(v[j].w);
                s0 += e0; p0 = fmaf(e0, gw, p0);
                s1 += e1; p1 = fmaf(e1, gw, p1);
                s2 += e2; p2 = fmaf(e2, gw, p2);
                s3 += e3; p3 = fmaf(e3, gw, p3);
                gw += 1.0f;
            }
        }
        const int base = sg * 4;
        sS[gc][base + 0] = s0;  sP[gc][base + 0] = p0;
        sS[gc][base + 1] = s1;  sP[gc][base + 1] = p1;
        sS[gc][base + 2] = s2;  sP[gc][base + 2] = p2;
        sS[gc][base + 3] = s3;  sP[gc][base + 3] = p3;
    }

    // ---- Phase 2: parse top/down per lane (threads 0..3) ----
    if (tid < CC) {
        const int* lp = labels + (size_t)n * RC + tid;  // int32 labels
        int  top = 0, first_trans = -1;
        bool any_valid = false, prev = false;
        bool v0 = false, v1 = false, vlast = false;
        #pragma unroll
        for (int r = 0; r < RR; ++r) {
            bool v = (lp[r * CC] < GG);
            if (v && !any_valid) { top = r; any_valid = true; }
            if (r > 0 && prev && !v && first_trans < 0) first_trans = r - 1;
            if (r == 0)      v0 = v;
            if (r == 1)      v1 = v;
            if (r == RR - 1) vlast = v;
            prev = v;
        }
        bool trans0 = v0 && !v1;
        int down = trans0 ? 0
                 : (vlast ? (RR - 1)
                 : (first_trans >= 0 ? first_trans : 0));
        if (!any_valid) { top = 0; down = 0; }
        s_top[tid]  = top;
        s_down[tid] = down;
    }
    __syncthreads();

    // Combine gc-partials -> pos per slot
    {
        float s = sS[0][tid] + sS[1][tid] + sS[2][tid] + sS[3][tid];
        float p = sP[0][tid] + sP[1][tid] + sP[2][tid] + sP[3][tid];
        s_pos[tid] = p / s;
    }
    __syncthreads();

    // ---- Phase 3: per-image loss (thread 0) ----
    if (tid == 0) {
        int tl = max(s_top[0],  max(s_top[1],  s_top[2]));
        int dl = min(s_down[0], min(s_down[1], s_down[2]));
        int tr = max(s_top[1],  max(s_top[2],  s_top[3]));
        int dr = min(s_down[1], min(s_down[2], s_down[3]));
        bool al = (tl < dl);
        bool ar = (tr < dr);

        float contrib = 0.0f;
        if (al) {
            float sl = 0.0f;
            for (int r = tl; r <= dl; ++r) {
                const float* p = &s_pos[r * CC];
                sl += fabsf(p[0] - 2.0f * p[1] + p[2]);
            }
            contrib += sl / (float)(dl - tl + 1);
        }
        if (ar) {
            float sr = 0.0f;
            for (int r = tr; r <= dr; ++r) {
                const float* p = &s_pos[r * CC];
                sr += fabsf(p[1] - 2.0f * p[2] + p[3]);
            }
            contrib += sr / (float)(dr - tr + 1);
        }
        float denom = (al && ar) ? (2.0f * (float)RR) : (float)RR;
        g_loss[n] = contrib / denom;

        __threadfence();
        unsigned int old = atomicAdd(&g_count, 1u);
        s_last = (old == NIMG - 1);
    }
    __syncthreads();

    // ---- Phase 4: last block reduces all per-image losses ----
    if (s_last) {
        float sum = 0.0f;
        int   cnt = 0;
        #pragma unroll
        for (int k = 0; k < 4; ++k) {
            int i = tid + k * RC;              // covers 0..1151
            if (i < NIMG) {
                float v = g_loss[i];
                sum += v;
                cnt += (v != 0.0f) ? 1 : 0;
            }
        }
        #pragma unroll
        for (int o = 16; o > 0; o >>= 1) {
            sum += __shfl_down_sync(0xffffffffu, sum, o);
            cnt += __shfl_down_sync(0xffffffffu, cnt, o);
        }
        __shared__ float wsum[9];
        __shared__ int   wcnt[9];
        const int wid = tid >> 5, lid = tid & 31;
        if (lid == 0) { wsum[wid] = sum; wcnt[wid] = cnt; }
        __syncthreads();
        if (tid == 0) {
            float ts = 0.0f; int tc = 0;
            #pragma unroll
            for (int w = 0; w < 9; ++w) { ts += wsum[w]; tc += wcnt[w]; }
            out[0] = (tc > 0) ? (ts / (float)tc) : 0.0f;
            g_count = 0;   // reset for next graph replay
        }
    }
}

extern "C" void kernel_launch(void* const* d_in, const int* in_sizes, int n_in,
                              void* d_out, int out_size)
{
    const float* x      = (const float*)d_in[0];   // [1024, 201, 72, 4] f32
    const int*   labels = (const int*)d_in[1];     // [1024, 72, 4] int32
    float*       out    = (float*)d_out;           // scalar f32

    lane_loss_kernel<<<NIMG, RC>>>(x, labels, out);
}